// round 1
// baseline (speedup 1.0000x reference)
#include <cuda_runtime.h>
#include <math.h>

// ---------------- problem constants ----------------
#define T_STEPS 50
#define BB      1024      // batch
#define S_DIM   32
#define D_DIM   600
#define H_DIM   600
#define A_DIM   6
#define E_DIM   1024
#define G3_DIM  1800      // 3*D
#define MIN_STD 0.1f

// output layout: concat of flattened outputs in tuple order
// (pm, ps, prior_stoch, det, qm, qs, post_stoch, det)
#define SZ_SB   ((size_t)T_STEPS * BB * S_DIM)   // 1,638,400
#define SZ_DB   ((size_t)T_STEPS * BB * D_DIM)   // 30,720,000
#define OFF_PM    ((size_t)0)
#define OFF_PS    (SZ_SB)
#define OFF_PRIOR (2 * SZ_SB)
#define OFF_DET1  (3 * SZ_SB)
#define OFF_QM    (3 * SZ_SB + SZ_DB)
#define OFF_QS    (4 * SZ_SB + SZ_DB)
#define OFF_POST  (5 * SZ_SB + SZ_DB)
#define OFF_DET2  (6 * SZ_SB + SZ_DB)

// ---------------- device scratch (static, no allocation) ----------------
__device__ float g_gi [BB * G3_DIM];          // 7.37 MB
__device__ float g_gh [BB * G3_DIM];          // 7.37 MB
__device__ float g_rnn[BB * H_DIM];           // 2.46 MB
__device__ float g_hp [BB * H_DIM];
__device__ float g_hq [BB * H_DIM];
__device__ float g_oP [BB * 2 * S_DIM];
__device__ float g_oQ [BB * 2 * S_DIM];
__device__ float g_enc[(size_t)T_STEPS * BB * D_DIM];  // 122.9 MB: enc @ Wq1_enc^T

// ---------------- math helpers ----------------
__device__ __forceinline__ float eluf(float x) {
    return x > 0.f ? x : expm1f(x);
}
__device__ __forceinline__ float sigmoidf_(float x) {
    return 1.f / (1.f + expf(-x));
}
__device__ __forceinline__ float softplusf_(float x) {
    // stable: max(x,0) + log1p(exp(-|x|))
    return fmaxf(x, 0.f) + log1pf(expf(-fabsf(x)));
}

// ---------------- generic TN GEMM: C[M,N] = act(A[M,K] @ W[N,K]^T + bias + extra) ----------------
// blockIdx.z selects between two independent param sets (shared M,N,K,act).
struct GemmSet {
    const float* A;      // [M,K], row stride K
    const float* W;      // [N, ldw], row-major, first K cols used
    const float* bias;   // [N] or null
    const float* extra;  // [M,N] addend (row stride N) or null
    float*       C;      // [M,N]
    int          ldw;
};

__global__ __launch_bounds__(256)
void gemm_tn_64(GemmSet s0, GemmSet s1, int M, int N, int K, int act) {
    constexpr int BM = 64, BN = 64, BK = 8, TM = 4, TN = 4;
    GemmSet s = (blockIdx.z == 0) ? s0 : s1;

    __shared__ float As[BK][BM];
    __shared__ float Ws[BK][BN];

    const int bm  = blockIdx.y * BM;
    const int bn  = blockIdx.x * BN;
    const int tid = threadIdx.x;

    // loader indices: each thread loads a float2 of A and of W per K-tile
    const int lrow = tid >> 2;          // 0..63
    const int lcol = (tid & 3) * 2;     // 0,2,4,6

    const int ty = tid >> 4;            // 0..15  (M direction)
    const int tx = tid & 15;            // 0..15  (N direction)

    float acc[TM][TN];
#pragma unroll
    for (int i = 0; i < TM; i++)
#pragma unroll
        for (int j = 0; j < TN; j++) acc[i][j] = 0.f;

    const bool wvalid = (bn + lrow) < N;
    const float* Aptr = s.A + (size_t)(bm + lrow) * K + lcol;
    const float* Wptr = s.W + (size_t)(bn + lrow) * s.ldw + lcol;

    for (int k0 = 0; k0 < K; k0 += BK) {
        float2 av = *(const float2*)(Aptr + k0);
        float2 wv = make_float2(0.f, 0.f);
        if (wvalid) wv = *(const float2*)(Wptr + k0);
        As[lcol][lrow]     = av.x;
        As[lcol + 1][lrow] = av.y;
        Ws[lcol][lrow]     = wv.x;
        Ws[lcol + 1][lrow] = wv.y;
        __syncthreads();

#pragma unroll
        for (int kk = 0; kk < BK; kk++) {
            float a[TM], w[TN];
            *(float4*)a = *(const float4*)&As[kk][ty * TM];
            *(float4*)w = *(const float4*)&Ws[kk][tx * TN];
#pragma unroll
            for (int i = 0; i < TM; i++)
#pragma unroll
                for (int j = 0; j < TN; j++)
                    acc[i][j] = fmaf(a[i], w[j], acc[i][j]);
        }
        __syncthreads();
    }

#pragma unroll
    for (int i = 0; i < TM; i++) {
        const int row = bm + ty * TM + i;
#pragma unroll
        for (int j = 0; j < TN; j++) {
            const int col = bn + tx * TN + j;
            if (col < N) {
                float v = acc[i][j];
                if (s.bias)  v += s.bias[col];
                if (s.extra) v += s.extra[(size_t)row * N + col];
                if (act) v = eluf(v);
                s.C[(size_t)row * N + col] = v;
            }
        }
    }
}

// ---------------- step kernels ----------------
// rnn_in[b,h] = elu(b_in[h] + act[b,:6] . W_in[h,:6] + stoch[b,:32] . W_in[h,6:38])
__global__ void rnn_in_kernel(const float* __restrict__ act,     // [B, 6]
                              const float* __restrict__ stoch,   // [B, 32]
                              const float* __restrict__ W_in,    // [600, 38]
                              const float* __restrict__ b_in,    // [600]
                              float* __restrict__ out)           // [B, 600]
{
    const int h = blockIdx.x;                              // 0..599
    const int b = blockIdx.y * blockDim.x + threadIdx.x;   // 0..1023
    __shared__ float w[A_DIM + S_DIM];
    if (threadIdx.x < A_DIM + S_DIM) w[threadIdx.x] = W_in[h * (A_DIM + S_DIM) + threadIdx.x];
    __syncthreads();

    float acc = b_in[h];
    const float* ab = act + (size_t)b * A_DIM;
#pragma unroll
    for (int a = 0; a < A_DIM; a++) acc = fmaf(ab[a], w[a], acc);
    const float* sb = stoch + (size_t)b * S_DIM;
#pragma unroll
    for (int si = 0; si < S_DIM; si++) acc = fmaf(sb[si], w[A_DIM + si], acc);
    out[(size_t)b * H_DIM + h] = eluf(acc);
}

// GRU gates + state update; writes det_new to both output slots
__global__ void gru_gate_kernel(const float* __restrict__ gi,        // [B, 1800] incl b_ih
                                const float* __restrict__ gh,        // [B, 1800] incl b_hh
                                const float* __restrict__ det_prev,  // [B, 600]
                                float* __restrict__ det_out1,
                                float* __restrict__ det_out2)
{
    const int idx = blockIdx.x * blockDim.x + threadIdx.x;
    if (idx >= BB * D_DIM) return;
    const int b = idx / D_DIM;
    const int j = idx % D_DIM;
    const float* gib = gi + (size_t)b * G3_DIM;
    const float* ghb = gh + (size_t)b * G3_DIM;
    const float r = sigmoidf_(gib[j] + ghb[j]);
    const float z = sigmoidf_(gib[D_DIM + j] + ghb[D_DIM + j]);
    const float n = tanhf(gib[2 * D_DIM + j] + r * ghb[2 * D_DIM + j]);
    const float d = (1.f - z) * n + z * det_prev[idx];
    det_out1[idx] = d;
    det_out2[idx] = d;
}

// distribution heads epilogue: split (mean, std_raw), softplus+min_std, reparam sample
__global__ void dist_kernel(const float* __restrict__ oP,     // [B, 64]
                            const float* __restrict__ oQ,     // [B, 64]
                            const float* __restrict__ eps_p,  // [B, 32]
                            const float* __restrict__ eps_q,  // [B, 32]
                            float* __restrict__ pm_o, float* __restrict__ ps_o,
                            float* __restrict__ prior_o,
                            float* __restrict__ qm_o, float* __restrict__ qs_o,
                            float* __restrict__ post_o)
{
    const int idx = blockIdx.x * blockDim.x + threadIdx.x;
    if (idx >= BB * S_DIM) return;
    const int b = idx / S_DIM;
    const int s = idx % S_DIM;

    const float pm  = oP[(size_t)b * 2 * S_DIM + s];
    const float psr = oP[(size_t)b * 2 * S_DIM + S_DIM + s];
    const float ps  = softplusf_(psr) + MIN_STD;
    pm_o[idx]    = pm;
    ps_o[idx]    = ps;
    prior_o[idx] = fmaf(ps, eps_p[idx], pm);

    const float qm  = oQ[(size_t)b * 2 * S_DIM + s];
    const float qsr = oQ[(size_t)b * 2 * S_DIM + S_DIM + s];
    const float qs  = softplusf_(qsr) + MIN_STD;
    qm_o[idx]   = qm;
    qs_o[idx]   = qs;
    post_o[idx] = fmaf(qs, eps_q[idx], qm);
}

// ---------------- host launcher ----------------
extern "C" void kernel_launch(void* const* d_in, const int* in_sizes, int n_in,
                              void* d_out, int out_size) {
    const float* encoded    = (const float*)d_in[1];   // [T,B,1024]
    const float* actions    = (const float*)d_in[2];   // [T,B,6]
    const float* init_stoch = (const float*)d_in[3];   // [B,32]
    const float* init_det   = (const float*)d_in[4];   // [B,600]
    const float* noise_p    = (const float*)d_in[5];   // [T,B,32]
    const float* noise_q    = (const float*)d_in[6];   // [T,B,32]
    const float* W_in = (const float*)d_in[7];         // [600,38]
    const float* b_in = (const float*)d_in[8];         // [600]
    const float* W_ih = (const float*)d_in[9];         // [1800,600]
    const float* W_hh = (const float*)d_in[10];        // [1800,600]
    const float* b_ih = (const float*)d_in[11];        // [1800]
    const float* b_hh = (const float*)d_in[12];        // [1800]
    const float* Wp1  = (const float*)d_in[13];        // [600,600]
    const float* bp1  = (const float*)d_in[14];
    const float* Wp2  = (const float*)d_in[15];        // [64,600]
    const float* bp2  = (const float*)d_in[16];
    const float* Wq1  = (const float*)d_in[17];        // [600,1624]
    const float* bq1  = (const float*)d_in[18];
    const float* Wq2  = (const float*)d_in[19];        // [64,600]
    const float* bq2  = (const float*)d_in[20];
    float* out = (float*)d_out;

    float *gi, *gh, *rnn, *hp, *hq, *oP, *oQ, *genc;
    cudaGetSymbolAddress((void**)&gi,   g_gi);
    cudaGetSymbolAddress((void**)&gh,   g_gh);
    cudaGetSymbolAddress((void**)&rnn,  g_rnn);
    cudaGetSymbolAddress((void**)&hp,   g_hp);
    cudaGetSymbolAddress((void**)&hq,   g_hq);
    cudaGetSymbolAddress((void**)&oP,   g_oP);
    cudaGetSymbolAddress((void**)&oQ,   g_oQ);
    cudaGetSymbolAddress((void**)&genc, g_enc);

    // -------- precompute (parallel over all T): genc = enc @ Wq1[:,600:]^T --------
    {
        GemmSet s{encoded, Wq1 + D_DIM, nullptr, nullptr, genc, D_DIM + E_DIM};
        dim3 grid((D_DIM + 63) / 64, (T_STEPS * BB) / 64, 1);
        gemm_tn_64<<<grid, 256>>>(s, s, T_STEPS * BB, D_DIM, E_DIM, 0);
    }

    // -------- sequential rollout --------
    for (int t = 0; t < T_STEPS; t++) {
        const float* stoch_prev = (t == 0) ? init_stoch
                                           : out + OFF_POST + (size_t)(t - 1) * BB * S_DIM;
        const float* det_prev   = (t == 0) ? init_det
                                           : out + OFF_DET1 + (size_t)(t - 1) * BB * D_DIM;
        float* det1 = out + OFF_DET1 + (size_t)t * BB * D_DIM;
        float* det2 = out + OFF_DET2 + (size_t)t * BB * D_DIM;

        // input MLP
        rnn_in_kernel<<<dim3(H_DIM, BB / 256), 256>>>(
            actions + (size_t)t * BB * A_DIM, stoch_prev, W_in, b_in, rnn);

        // GRU pre-activations: gi = rnn @ W_ih^T + b_ih ; gh = det_prev @ W_hh^T + b_hh
        {
            GemmSet sA{rnn,      W_ih, b_ih, nullptr, gi, H_DIM};
            GemmSet sB{det_prev, W_hh, b_hh, nullptr, gh, D_DIM};
            dim3 grid((G3_DIM + 63) / 64, BB / 64, 2);
            gemm_tn_64<<<grid, 256>>>(sA, sB, BB, G3_DIM, H_DIM, 0);
        }

        // gates -> det_new (written directly to both det output slots)
        gru_gate_kernel<<<(BB * D_DIM + 255) / 256, 256>>>(gi, gh, det_prev, det1, det2);

        // hidden layers: hp = elu(det @ Wp1^T + bp1); hq = elu(det @ Wq1[:,:600]^T + genc_t + bq1)
        {
            GemmSet sP{det1, Wp1, bp1, nullptr, hp, D_DIM};
            GemmSet sQ{det1, Wq1, bq1, genc + (size_t)t * BB * D_DIM, hq, D_DIM + E_DIM};
            dim3 grid((H_DIM + 63) / 64, BB / 64, 2);
            gemm_tn_64<<<grid, 256>>>(sP, sQ, BB, H_DIM, D_DIM, 1);
        }

        // output heads: oP = hp @ Wp2^T + bp2 ; oQ = hq @ Wq2^T + bq2
        {
            GemmSet sP{hp, Wp2, bp2, nullptr, oP, H_DIM};
            GemmSet sQ{hq, Wq2, bq2, nullptr, oQ, H_DIM};
            dim3 grid(1, BB / 64, 2);
            gemm_tn_64<<<grid, 256>>>(sP, sQ, BB, 2 * S_DIM, H_DIM, 0);
        }

        // distributions + reparam samples (post_stoch doubles as next-step carry)
        dist_kernel<<<(BB * S_DIM + 255) / 256, 256>>>(
            oP, oQ,
            noise_p + (size_t)t * BB * S_DIM, noise_q + (size_t)t * BB * S_DIM,
            out + OFF_PM    + (size_t)t * BB * S_DIM,
            out + OFF_PS    + (size_t)t * BB * S_DIM,
            out + OFF_PRIOR + (size_t)t * BB * S_DIM,
            out + OFF_QM    + (size_t)t * BB * S_DIM,
            out + OFF_QS    + (size_t)t * BB * S_DIM,
            out + OFF_POST  + (size_t)t * BB * S_DIM);
    }
}

// round 4
// speedup vs baseline: 1.9396x; 1.9396x over previous
#include <cuda_runtime.h>
#include <cuda_bf16.h>
#include <math.h>
#include <stdint.h>

#define T_STEPS 50
#define BB      1024
#define S_DIM   32
#define D_DIM   600
#define H_DIM   600
#define A_DIM   6
#define E_DIM   1024
#define G3_DIM  1800
#define MIN_STD 0.1f

#define SZ_SB   ((size_t)T_STEPS * BB * S_DIM)
#define SZ_DB   ((size_t)T_STEPS * BB * D_DIM)
#define OFF_PM    ((size_t)0)
#define OFF_PS    (SZ_SB)
#define OFF_PRIOR (2 * SZ_SB)
#define OFF_DET1  (3 * SZ_SB)
#define OFF_QM    (3 * SZ_SB + SZ_DB)
#define OFF_QS    (4 * SZ_SB + SZ_DB)
#define OFF_POST  (5 * SZ_SB + SZ_DB)
#define OFF_DET2  (6 * SZ_SB + SZ_DB)

// ---------------- static device scratch ----------------
__device__ __nv_bfloat16 g_Wih_h[G3_DIM * D_DIM], g_Wih_l[G3_DIM * D_DIM];
__device__ __nv_bfloat16 g_Whh_h[G3_DIM * D_DIM], g_Whh_l[G3_DIM * D_DIM];
__device__ __nv_bfloat16 g_Wp1_h[H_DIM * D_DIM],  g_Wp1_l[H_DIM * D_DIM];
__device__ __nv_bfloat16 g_Wq1d_h[H_DIM * D_DIM], g_Wq1d_l[H_DIM * D_DIM];
__device__ __nv_bfloat16 g_Wq1e_h[H_DIM * E_DIM], g_Wq1e_l[H_DIM * E_DIM];
__device__ __nv_bfloat16 g_Wp2_h[64 * H_DIM],     g_Wp2_l[64 * H_DIM];
__device__ __nv_bfloat16 g_Wq2_h[64 * H_DIM],     g_Wq2_l[64 * H_DIM];
__device__ __nv_bfloat16 g_enc_h[(size_t)T_STEPS * BB * E_DIM];
__device__ __nv_bfloat16 g_enc_l[(size_t)T_STEPS * BB * E_DIM];
__device__ float         g_genc[(size_t)T_STEPS * BB * D_DIM];
__device__ __nv_bfloat16 g_rnn_h[BB * H_DIM], g_rnn_l[BB * H_DIM];
__device__ __nv_bfloat16 g_det_h[BB * D_DIM], g_det_l[BB * D_DIM];
__device__ __nv_bfloat16 g_hp_h [BB * H_DIM], g_hp_l [BB * H_DIM];
__device__ __nv_bfloat16 g_hq_h [BB * H_DIM], g_hq_l [BB * H_DIM];
__device__ float g_gi[BB * G3_DIM], g_gh[BB * G3_DIM];
__device__ float g_oP[BB * 2 * S_DIM], g_oQ[BB * 2 * S_DIM];

__device__ __forceinline__ float eluf(float x)      { return x > 0.f ? x : expm1f(x); }
__device__ __forceinline__ float sigmoidf_(float x) { return 1.f / (1.f + expf(-x)); }
__device__ __forceinline__ float softplusf_(float x){ return fmaxf(x, 0.f) + log1pf(expf(-fabsf(x))); }

// ---------------- PTX helpers (baseline ISA only: sm_80-safe) ----------------
__device__ __forceinline__ uint32_t smem_u32(const void* p) {
    uint32_t a;
    asm("{ .reg .u64 t; cvta.to.shared.u64 t, %1; cvt.u32.u64 %0, t; }" : "=r"(a) : "l"(p));
    return a;
}
__device__ __forceinline__ void cpa16(uint32_t dst, const void* src, int nb) {
    asm volatile("cp.async.cg.shared.global [%0], [%1], 16, %2;" :: "r"(dst), "l"(src), "r"(nb));
}
#define CP_COMMIT() asm volatile("cp.async.commit_group;" ::: "memory")

__device__ __forceinline__ void ldsm4(uint32_t* r, uint32_t addr) {
    asm volatile("ldmatrix.sync.aligned.m8n8.x4.shared.b16 {%0,%1,%2,%3}, [%4];"
        : "=r"(r[0]), "=r"(r[1]), "=r"(r[2]), "=r"(r[3]) : "r"(addr));
}
__device__ __forceinline__ void mma16816(float* d, const uint32_t* a, const uint32_t* b) {
    asm volatile("mma.sync.aligned.m16n8k16.row.col.f32.bf16.bf16.f32 "
        "{%0,%1,%2,%3}, {%4,%5,%6,%7}, {%8,%9}, {%0,%1,%2,%3};"
        : "+f"(d[0]), "+f"(d[1]), "+f"(d[2]), "+f"(d[3])
        : "r"(a[0]), "r"(a[1]), "r"(a[2]), "r"(a[3]), "r"(b[0]), "r"(b[1]));
}

// ---------------- bf16 hi/lo 3-term GEMM: C[M,N] = act(A[M,K] @ W[N,K]^T + bias + extra) ----
// M multiple of 128; any N (row-predicated); K*2 multiple of 16 bytes.
struct TSet {
    const __nv_bfloat16 *Ahi, *Alo;   // [M,K]
    const __nv_bfloat16 *Whi, *Wlo;   // [N,K]
    const float *bias;                // [N] or null
    const float *extra;               // [M,N] or null
    float *Cf;                        // fp32 out or null
    __nv_bfloat16 *Chi, *Clo;         // bf16-split out or null
};

#define BMT 128
#define BNT 64
#define RSB 80                        // smem row stride bytes (64B data + 16B pad)
#define ASZ (BMT * RSB)               // 10240
#define WSZ (BNT * RSB)               // 5120
#define STG (2 * ASZ + 2 * WSZ)       // 30720
#define SMEM_GEMM (2 * STG)           // 61440

__global__ void __launch_bounds__(256, 2)
mma_gemm(TSet s0, TSet s1, int N, int K, int KC, int act)
{
    extern __shared__ char smraw[];
    const TSet s = blockIdx.z ? s1 : s0;
    const int tid = threadIdx.x;
    const int m0 = blockIdx.y * BMT, n0 = blockIdx.x * BNT;
    const uint32_t sb = smem_u32(smraw);
    const int Kb = K * 2;

    const int wid = tid >> 5, lane = tid & 31;
    const int wm = wid & 3;           // 4 warps along M (32 rows each)
    const int wn = wid >> 2;          // 2 warps along N (32 cols each)

    // ldmatrix per-lane address components
    const int arow  = lane & 15;                       // A: rows of m16 tile
    const int akoff = (lane >> 4) * 16;                // A: k8 half select
    const int brow  = (lane & 7) + ((lane >> 4) << 3); // B: n rows (0-7 / 8-15)
    const int bkoff = ((lane >> 3) & 1) * 16;          // B: k8 half select

    float acc[2][4][4];
#pragma unroll
    for (int i = 0; i < 2; i++)
#pragma unroll
        for (int j = 0; j < 4; j++)
#pragma unroll
            for (int q = 0; q < 4; q++) acc[i][j][q] = 0.f;

    auto load_stage = [&](int kc) {
        const uint32_t base = sb + (uint32_t)(kc & 1) * STG;
        // A hi|lo : 128 rows x 64B (2 bufs x 128 rows x 4 chunks = 1024 cp)
        #pragma unroll
        for (int v = 0; v < 4; v++) {
            const int idx  = v * 256 + tid;
            const int half = idx >> 9, r = (idx >> 2) & 127, j = idx & 3;
            const int off  = kc * 64 + j * 16;
            const char* src = (const char*)(half ? s.Alo : s.Ahi);
            const int nb = (off + 16 <= Kb) ? 16 : 0;
            const char* p = nb ? src + (size_t)(m0 + r) * Kb + off : src;
            cpa16(base + half * ASZ + r * RSB + j * 16, p, nb);
        }
        // W hi|lo : 64 rows x 64B (512 cp)
        #pragma unroll
        for (int v = 0; v < 2; v++) {
            const int idx  = v * 256 + tid;
            const int half = idx >> 8, r = (idx >> 2) & 63, j = idx & 3;
            const int off  = kc * 64 + j * 16;
            const char* src = (const char*)(half ? s.Wlo : s.Whi);
            const int nb = (off + 16 <= Kb && (n0 + r) < N) ? 16 : 0;
            const char* p = nb ? src + (size_t)(n0 + r) * Kb + off : src;
            cpa16(base + 2 * ASZ + half * WSZ + r * RSB + j * 16, p, nb);
        }
        CP_COMMIT();
    };

    load_stage(0);
    for (int kc = 0; kc < KC; kc++) {
        if (kc + 1 < KC) { load_stage(kc + 1); asm volatile("cp.async.wait_group 1;" ::: "memory"); }
        else             {                      asm volatile("cp.async.wait_group 0;" ::: "memory"); }
        __syncthreads();
        const uint32_t base = sb + (uint32_t)(kc & 1) * STG;

        #pragma unroll
        for (int k16 = 0; k16 < 2; k16++) {
            uint32_t a_h[2][4], a_l[2][4], b_h[2][4], b_l[2][4];
            const uint32_t Ah0 = base + (wm * 32 + arow) * RSB + k16 * 32 + akoff;
            ldsm4(a_h[0], Ah0);           ldsm4(a_h[1], Ah0 + 16 * RSB);
            ldsm4(a_l[0], Ah0 + ASZ);     ldsm4(a_l[1], Ah0 + ASZ + 16 * RSB);
            const uint32_t Wh0 = base + 2 * ASZ + (wn * 32 + brow) * RSB + k16 * 32 + bkoff;
            ldsm4(b_h[0], Wh0);           ldsm4(b_h[1], Wh0 + 16 * RSB);
            ldsm4(b_l[0], Wh0 + WSZ);     ldsm4(b_l[1], Wh0 + WSZ + 16 * RSB);

            #pragma unroll
            for (int tm = 0; tm < 2; tm++)
                #pragma unroll
                for (int g = 0; g < 2; g++)
                    #pragma unroll
                    for (int sub = 0; sub < 2; sub++) {
                        float* d = acc[tm][g * 2 + sub];
                        mma16816(d, a_h[tm], &b_h[g][sub * 2]);   // Ah*Wh
                        mma16816(d, a_h[tm], &b_l[g][sub * 2]);   // Ah*Wl
                        mma16816(d, a_l[tm], &b_h[g][sub * 2]);   // Al*Wh
                    }
        }
        __syncthreads();   // all warps done reading this buffer before it is reloaded
    }

    // ---------------- fused epilogue from fragments ----------------
    #pragma unroll
    for (int nt = 0; nt < 4; nt++) {
        const int gc = n0 + wn * 32 + nt * 8 + ((lane & 3) << 1);
        if (gc >= N) continue;     // N even; gc even => gc+1 also < N
        const float b0 = s.bias ? s.bias[gc]     : 0.f;
        const float b1 = s.bias ? s.bias[gc + 1] : 0.f;
        #pragma unroll
        for (int tm = 0; tm < 2; tm++) {
            const int r0 = m0 + wm * 32 + tm * 16 + (lane >> 2);
            #pragma unroll
            for (int hh = 0; hh < 2; hh++) {
                const int gr = r0 + hh * 8;
                float v0 = acc[tm][nt][hh * 2 + 0] + b0;
                float v1 = acc[tm][nt][hh * 2 + 1] + b1;
                if (s.extra) {
                    v0 += s.extra[(size_t)gr * N + gc];
                    v1 += s.extra[(size_t)gr * N + gc + 1];
                }
                if (act) { v0 = eluf(v0); v1 = eluf(v1); }
                if (s.Cf) {
                    s.Cf[(size_t)gr * N + gc]     = v0;
                    s.Cf[(size_t)gr * N + gc + 1] = v1;
                }
                if (s.Chi) {
                    const __nv_bfloat16 h0 = __float2bfloat16(v0);
                    const __nv_bfloat16 h1 = __float2bfloat16(v1);
                    s.Chi[(size_t)gr * N + gc]     = h0;
                    s.Chi[(size_t)gr * N + gc + 1] = h1;
                    s.Clo[(size_t)gr * N + gc]     = __float2bfloat16(v0 - __bfloat162float(h0));
                    s.Clo[(size_t)gr * N + gc + 1] = __float2bfloat16(v1 - __bfloat162float(h1));
                }
            }
        }
    }
}

// ---------------- prep: fp32 -> bf16 hi/lo split (sub-matrix of pitched src) ----------------
__global__ void wprep(const float* __restrict__ src, int pitch, int c0, int rows, int K,
                      __nv_bfloat16* __restrict__ hi, __nv_bfloat16* __restrict__ lo)
{
    const int total = rows * K;
    for (int i = blockIdx.x * blockDim.x + threadIdx.x; i < total; i += gridDim.x * blockDim.x) {
        const float v = src[(size_t)(i / K) * pitch + c0 + (i % K)];
        const __nv_bfloat16 h = __float2bfloat16(v);
        hi[i] = h;
        lo[i] = __float2bfloat16(v - __bfloat162float(h));
    }
}

// ---------------- elementwise step kernels ----------------
__global__ void rnn_in_kernel(const float* __restrict__ act, const float* __restrict__ stoch,
                              const float* __restrict__ W_in, const float* __restrict__ b_in,
                              __nv_bfloat16* __restrict__ ohi, __nv_bfloat16* __restrict__ olo)
{
    const int h = blockIdx.x;
    const int b = blockIdx.y * blockDim.x + threadIdx.x;
    __shared__ float w[A_DIM + S_DIM];
    if (threadIdx.x < A_DIM + S_DIM) w[threadIdx.x] = W_in[h * (A_DIM + S_DIM) + threadIdx.x];
    __syncthreads();
    float acc = b_in[h];
    const float* ab = act + (size_t)b * A_DIM;
#pragma unroll
    for (int a = 0; a < A_DIM; a++) acc = fmaf(ab[a], w[a], acc);
    const float* sp = stoch + (size_t)b * S_DIM;
#pragma unroll
    for (int si = 0; si < S_DIM; si++) acc = fmaf(sp[si], w[A_DIM + si], acc);
    const float v = eluf(acc);
    const __nv_bfloat16 hh = __float2bfloat16(v);
    ohi[(size_t)b * H_DIM + h] = hh;
    olo[(size_t)b * H_DIM + h] = __float2bfloat16(v - __bfloat162float(hh));
}

__global__ void gru_gate_kernel(const float* __restrict__ gi, const float* __restrict__ gh,
                                const float* __restrict__ det_prev,
                                float* __restrict__ o1, float* __restrict__ o2,
                                __nv_bfloat16* __restrict__ dhi, __nv_bfloat16* __restrict__ dlo)
{
    const int idx = blockIdx.x * blockDim.x + threadIdx.x;
    if (idx >= BB * D_DIM) return;
    const int b = idx / D_DIM, j = idx % D_DIM;
    const float* gib = gi + (size_t)b * G3_DIM;
    const float* ghb = gh + (size_t)b * G3_DIM;
    const float r = sigmoidf_(gib[j] + ghb[j]);
    const float z = sigmoidf_(gib[D_DIM + j] + ghb[D_DIM + j]);
    const float n = tanhf(gib[2 * D_DIM + j] + r * ghb[2 * D_DIM + j]);
    const float d = (1.f - z) * n + z * det_prev[idx];
    o1[idx] = d; o2[idx] = d;
    const __nv_bfloat16 hh = __float2bfloat16(d);
    dhi[idx] = hh;
    dlo[idx] = __float2bfloat16(d - __bfloat162float(hh));
}

__global__ void dist_kernel(const float* __restrict__ oP, const float* __restrict__ oQ,
                            const float* __restrict__ ep, const float* __restrict__ eq,
                            float* __restrict__ pm_o, float* __restrict__ ps_o, float* __restrict__ pr_o,
                            float* __restrict__ qm_o, float* __restrict__ qs_o, float* __restrict__ po_o)
{
    const int idx = blockIdx.x * blockDim.x + threadIdx.x;
    if (idx >= BB * S_DIM) return;
    const int b = idx / S_DIM, sx = idx % S_DIM;
    const float pm = oP[(size_t)b * 64 + sx];
    const float ps = softplusf_(oP[(size_t)b * 64 + 32 + sx]) + MIN_STD;
    pm_o[idx] = pm; ps_o[idx] = ps; pr_o[idx] = fmaf(ps, ep[idx], pm);
    const float qm = oQ[(size_t)b * 64 + sx];
    const float qs = softplusf_(oQ[(size_t)b * 64 + 32 + sx]) + MIN_STD;
    qm_o[idx] = qm; qs_o[idx] = qs; po_o[idx] = fmaf(qs, eq[idx], qm);
}

// ---------------- host launcher ----------------
extern "C" void kernel_launch(void* const* d_in, const int* in_sizes, int n_in,
                              void* d_out, int out_size) {
    const float* encoded    = (const float*)d_in[1];
    const float* actions    = (const float*)d_in[2];
    const float* init_stoch = (const float*)d_in[3];
    const float* init_det   = (const float*)d_in[4];
    const float* noise_p    = (const float*)d_in[5];
    const float* noise_q    = (const float*)d_in[6];
    const float* W_in = (const float*)d_in[7];
    const float* b_in = (const float*)d_in[8];
    const float* W_ih = (const float*)d_in[9];
    const float* W_hh = (const float*)d_in[10];
    const float* b_ih = (const float*)d_in[11];
    const float* b_hh = (const float*)d_in[12];
    const float* Wp1  = (const float*)d_in[13];
    const float* bp1  = (const float*)d_in[14];
    const float* Wp2  = (const float*)d_in[15];
    const float* bp2  = (const float*)d_in[16];
    const float* Wq1  = (const float*)d_in[17];
    const float* bq1  = (const float*)d_in[18];
    const float* Wq2  = (const float*)d_in[19];
    const float* bq2  = (const float*)d_in[20];
    float* out = (float*)d_out;

    __nv_bfloat16 *Wih_h, *Wih_l, *Whh_h, *Whh_l, *Wp1_h, *Wp1_l, *Wq1d_h, *Wq1d_l;
    __nv_bfloat16 *Wq1e_h, *Wq1e_l, *Wp2_h, *Wp2_l, *Wq2_h, *Wq2_l;
    __nv_bfloat16 *enc_h, *enc_l, *rnn_h, *rnn_l, *det_h, *det_l, *hp_h, *hp_l, *hq_h, *hq_l;
    float *genc, *gi, *gh, *oP, *oQ;
    cudaGetSymbolAddress((void**)&Wih_h, g_Wih_h);   cudaGetSymbolAddress((void**)&Wih_l, g_Wih_l);
    cudaGetSymbolAddress((void**)&Whh_h, g_Whh_h);   cudaGetSymbolAddress((void**)&Whh_l, g_Whh_l);
    cudaGetSymbolAddress((void**)&Wp1_h, g_Wp1_h);   cudaGetSymbolAddress((void**)&Wp1_l, g_Wp1_l);
    cudaGetSymbolAddress((void**)&Wq1d_h, g_Wq1d_h); cudaGetSymbolAddress((void**)&Wq1d_l, g_Wq1d_l);
    cudaGetSymbolAddress((void**)&Wq1e_h, g_Wq1e_h); cudaGetSymbolAddress((void**)&Wq1e_l, g_Wq1e_l);
    cudaGetSymbolAddress((void**)&Wp2_h, g_Wp2_h);   cudaGetSymbolAddress((void**)&Wp2_l, g_Wp2_l);
    cudaGetSymbolAddress((void**)&Wq2_h, g_Wq2_h);   cudaGetSymbolAddress((void**)&Wq2_l, g_Wq2_l);
    cudaGetSymbolAddress((void**)&enc_h, g_enc_h);   cudaGetSymbolAddress((void**)&enc_l, g_enc_l);
    cudaGetSymbolAddress((void**)&rnn_h, g_rnn_h);   cudaGetSymbolAddress((void**)&rnn_l, g_rnn_l);
    cudaGetSymbolAddress((void**)&det_h, g_det_h);   cudaGetSymbolAddress((void**)&det_l, g_det_l);
    cudaGetSymbolAddress((void**)&hp_h, g_hp_h);     cudaGetSymbolAddress((void**)&hp_l, g_hp_l);
    cudaGetSymbolAddress((void**)&hq_h, g_hq_h);     cudaGetSymbolAddress((void**)&hq_l, g_hq_l);
    cudaGetSymbolAddress((void**)&genc, g_genc);
    cudaGetSymbolAddress((void**)&gi, g_gi);         cudaGetSymbolAddress((void**)&gh, g_gh);
    cudaGetSymbolAddress((void**)&oP, g_oP);         cudaGetSymbolAddress((void**)&oQ, g_oQ);

    cudaFuncSetAttribute(mma_gemm, cudaFuncAttributeMaxDynamicSharedMemorySize, SMEM_GEMM);

    // ---- once-per-replay prep: bf16 hi/lo splits ----
    wprep<<<4096, 256>>>(W_ih, D_DIM, 0, G3_DIM, D_DIM, Wih_h, Wih_l);
    wprep<<<4096, 256>>>(W_hh, D_DIM, 0, G3_DIM, D_DIM, Whh_h, Whh_l);
    wprep<<<2048, 256>>>(Wp1, D_DIM, 0, H_DIM, D_DIM, Wp1_h, Wp1_l);
    wprep<<<2048, 256>>>(Wq1, D_DIM + E_DIM, 0, H_DIM, D_DIM, Wq1d_h, Wq1d_l);
    wprep<<<2048, 256>>>(Wq1, D_DIM + E_DIM, D_DIM, H_DIM, E_DIM, Wq1e_h, Wq1e_l);
    wprep<<<256, 256>>>(Wp2, H_DIM, 0, 64, H_DIM, Wp2_h, Wp2_l);
    wprep<<<256, 256>>>(Wq2, H_DIM, 0, 64, H_DIM, Wq2_h, Wq2_l);
    wprep<<<16384, 256>>>(encoded, E_DIM, 0, T_STEPS * BB, E_DIM, enc_h, enc_l);
    wprep<<<2048, 256>>>(init_det, D_DIM, 0, BB, D_DIM, det_h, det_l);

    // ---- precompute genc = encoded @ Wq1[:,600:]^T   [51200 x 600], K=1024 ----
    {
        TSet s{enc_h, enc_l, Wq1e_h, Wq1e_l, nullptr, nullptr, genc, nullptr, nullptr};
        mma_gemm<<<dim3(10, T_STEPS * BB / BMT, 1), 256, SMEM_GEMM>>>(s, s, H_DIM, E_DIM, 32, 0);
    }

    // ---- sequential rollout ----
    for (int t = 0; t < T_STEPS; t++) {
        const float* stoch_prev = (t == 0) ? init_stoch : out + OFF_POST + (size_t)(t - 1) * BB * S_DIM;
        const float* det_prev_f = (t == 0) ? init_det   : out + OFF_DET1 + (size_t)(t - 1) * BB * D_DIM;
        float* det1 = out + OFF_DET1 + (size_t)t * BB * D_DIM;
        float* det2 = out + OFF_DET2 + (size_t)t * BB * D_DIM;

        rnn_in_kernel<<<dim3(H_DIM, BB / 256), 256>>>(
            actions + (size_t)t * BB * A_DIM, stoch_prev, W_in, b_in, rnn_h, rnn_l);

        {   // gi = rnn @ W_ih^T + b_ih ; gh = det_prev @ W_hh^T + b_hh   (N=1800, K=600)
            TSet sA{rnn_h, rnn_l, Wih_h, Wih_l, b_ih, nullptr, gi, nullptr, nullptr};
            TSet sB{det_h, det_l, Whh_h, Whh_l, b_hh, nullptr, gh, nullptr, nullptr};
            mma_gemm<<<dim3(29, BB / BMT, 2), 256, SMEM_GEMM>>>(sA, sB, G3_DIM, D_DIM, 19, 0);
        }

        gru_gate_kernel<<<(BB * D_DIM + 255) / 256, 256>>>(gi, gh, det_prev_f, det1, det2, det_h, det_l);

        {   // hp = elu(det @ Wp1^T + bp1) ; hq = elu(det @ Wq1d^T + genc_t + bq1)   (N=600, K=600)
            TSet sP{det_h, det_l, Wp1_h, Wp1_l, bp1, nullptr, nullptr, hp_h, hp_l};
            TSet sQ{det_h, det_l, Wq1d_h, Wq1d_l, bq1, genc + (size_t)t * BB * D_DIM, nullptr, hq_h, hq_l};
            mma_gemm<<<dim3(10, BB / BMT, 2), 256, SMEM_GEMM>>>(sP, sQ, H_DIM, D_DIM, 19, 1);
        }

        {   // oP = hp @ Wp2^T + bp2 ; oQ = hq @ Wq2^T + bq2   (N=64, K=600)
            TSet sP{hp_h, hp_l, Wp2_h, Wp2_l, bp2, nullptr, oP, nullptr, nullptr};
            TSet sQ{hq_h, hq_l, Wq2_h, Wq2_l, bq2, nullptr, oQ, nullptr, nullptr};
            mma_gemm<<<dim3(1, BB / BMT, 2), 256, SMEM_GEMM>>>(sP, sQ, 64, H_DIM, 19, 0);
        }

        dist_kernel<<<(BB * S_DIM + 255) / 256, 256>>>(
            oP, oQ,
            noise_p + (size_t)t * BB * S_DIM, noise_q + (size_t)t * BB * S_DIM,
            out + OFF_PM    + (size_t)t * BB * S_DIM,
            out + OFF_PS    + (size_t)t * BB * S_DIM,
            out + OFF_PRIOR + (size_t)t * BB * S_DIM,
            out + OFF_QM    + (size_t)t * BB * S_DIM,
            out + OFF_QS    + (size_t)t * BB * S_DIM,
            out + OFF_POST  + (size_t)t * BB * S_DIM);
    }
}

// round 5
// speedup vs baseline: 2.8188x; 1.4533x over previous
#include <cuda_runtime.h>
#include <cuda_bf16.h>
#include <math.h>
#include <stdint.h>

#define T_STEPS 50
#define BB      1024
#define S_DIM   32
#define D_DIM   600
#define H_DIM   600
#define A_DIM   6
#define E_DIM   1024
#define G3_DIM  1800
#define MIN_STD 0.1f

#define SZ_SB   ((size_t)T_STEPS * BB * S_DIM)
#define SZ_DB   ((size_t)T_STEPS * BB * D_DIM)
#define OFF_PM    ((size_t)0)
#define OFF_PS    (SZ_SB)
#define OFF_PRIOR (2 * SZ_SB)
#define OFF_DET1  (3 * SZ_SB)
#define OFF_QM    (3 * SZ_SB + SZ_DB)
#define OFF_QS    (4 * SZ_SB + SZ_DB)
#define OFF_POST  (5 * SZ_SB + SZ_DB)
#define OFF_DET2  (6 * SZ_SB + SZ_DB)

// ---------------- static device scratch ----------------
__device__ __nv_bfloat16 g_Wih_h[G3_DIM * D_DIM], g_Wih_l[G3_DIM * D_DIM];
__device__ __nv_bfloat16 g_Whh_h[G3_DIM * D_DIM], g_Whh_l[G3_DIM * D_DIM];
__device__ __nv_bfloat16 g_Wp1_h[H_DIM * D_DIM],  g_Wp1_l[H_DIM * D_DIM];
__device__ __nv_bfloat16 g_Wq1d_h[H_DIM * D_DIM], g_Wq1d_l[H_DIM * D_DIM];
__device__ __nv_bfloat16 g_Wq1e_h[H_DIM * E_DIM], g_Wq1e_l[H_DIM * E_DIM];
__device__ __nv_bfloat16 g_Wp2_h[64 * H_DIM],     g_Wp2_l[64 * H_DIM];
__device__ __nv_bfloat16 g_Wq2_h[64 * H_DIM],     g_Wq2_l[64 * H_DIM];
__device__ __nv_bfloat16 g_enc_h[(size_t)T_STEPS * BB * E_DIM];
__device__ __nv_bfloat16 g_enc_l[(size_t)T_STEPS * BB * E_DIM];
__device__ float         g_genc[(size_t)T_STEPS * BB * D_DIM];
__device__ __nv_bfloat16 g_rnn_h[BB * H_DIM], g_rnn_l[BB * H_DIM];
__device__ __nv_bfloat16 g_det_h[BB * D_DIM], g_det_l[BB * D_DIM];
__device__ __nv_bfloat16 g_hp_h [BB * H_DIM], g_hp_l [BB * H_DIM];
__device__ __nv_bfloat16 g_hq_h [BB * H_DIM], g_hq_l [BB * H_DIM];
__device__ float g_gi[BB * G3_DIM], g_gh[BB * G3_DIM];
__device__ float g_oP[BB * 2 * S_DIM], g_oQ[BB * 2 * S_DIM];

__device__ __forceinline__ float eluf(float x)      { return x > 0.f ? x : expm1f(x); }
__device__ __forceinline__ float sigmoidf_(float x) { return 1.f / (1.f + expf(-x)); }
__device__ __forceinline__ float softplusf_(float x){ return fmaxf(x, 0.f) + log1pf(expf(-fabsf(x))); }

// ---------------- PTX helpers (sm_80-safe baseline ISA) ----------------
__device__ __forceinline__ uint32_t smem_u32(const void* p) {
    uint32_t a;
    asm("{ .reg .u64 t; cvta.to.shared.u64 t, %1; cvt.u32.u64 %0, t; }" : "=r"(a) : "l"(p));
    return a;
}
__device__ __forceinline__ void cpa16(uint32_t dst, const void* src, int nb) {
    asm volatile("cp.async.cg.shared.global [%0], [%1], 16, %2;" :: "r"(dst), "l"(src), "r"(nb));
}
#define CP_COMMIT() asm volatile("cp.async.commit_group;" ::: "memory")

__device__ __forceinline__ void ldsm4(uint32_t* r, uint32_t addr) {
    asm volatile("ldmatrix.sync.aligned.m8n8.x4.shared.b16 {%0,%1,%2,%3}, [%4];"
        : "=r"(r[0]), "=r"(r[1]), "=r"(r[2]), "=r"(r[3]) : "r"(addr));
}
__device__ __forceinline__ void mma16816(float* d, const uint32_t* a, const uint32_t* b) {
    asm volatile("mma.sync.aligned.m16n8k16.row.col.f32.bf16.bf16.f32 "
        "{%0,%1,%2,%3}, {%4,%5,%6,%7}, {%8,%9}, {%0,%1,%2,%3};"
        : "+f"(d[0]), "+f"(d[1]), "+f"(d[2]), "+f"(d[3])
        : "r"(a[0]), "r"(a[1]), "r"(a[2]), "r"(a[3]), "r"(b[0]), "r"(b[1]));
}

// ---------------- bf16 hi/lo 3-term GEMM: C[M,N] = act(A[M,K] @ W[N,K]^T + bias + extra) ----
struct TSet {
    const __nv_bfloat16 *Ahi, *Alo;   // [M,K]
    const __nv_bfloat16 *Whi, *Wlo;   // [N,K]
    const float *bias;                // [N] or null
    const float *extra;               // [M,N] or null
    float *Cf;                        // fp32 out or null
    __nv_bfloat16 *Chi, *Clo;         // bf16-split out or null
};

#define BMT 128
#define BNT 64
#define RSB 144                       // row stride bytes: 128B data + 16B pad (bank-shift 4)
#define ASZ (BMT * RSB)               // 18432
#define WSZ (BNT * RSB)               // 9216
#define STG (2 * ASZ + 2 * WSZ)       // 55296
#define SMEM_GEMM (2 * STG)           // 110592

__global__ void __launch_bounds__(256, 2)
mma_gemm(TSet s0, TSet s1, int N, int K, int KC, int act)
{
    extern __shared__ char smraw[];
    const TSet s = blockIdx.z ? s1 : s0;
    const int tid = threadIdx.x;
    const int m0 = blockIdx.y * BMT, n0 = blockIdx.x * BNT;
    const uint32_t sb = smem_u32(smraw);
    const int Kb = K * 2;

    const int wid = tid >> 5, lane = tid & 31;
    const int wm = wid & 3;           // 4 warps along M (32 rows each)
    const int wn = wid >> 2;          // 2 warps along N (32 cols each)

    const int arow  = lane & 15;
    const int akoff = (lane >> 4) * 16;
    const int brow  = (lane & 7) + ((lane >> 4) << 3);
    const int bkoff = ((lane >> 3) & 1) * 16;

    float acc[2][4][4];
#pragma unroll
    for (int i = 0; i < 2; i++)
#pragma unroll
        for (int j = 0; j < 4; j++)
#pragma unroll
            for (int q = 0; q < 4; q++) acc[i][j][q] = 0.f;

    auto load_stage = [&](int kc) {
        const uint32_t base = sb + (uint32_t)(kc & 1) * STG;
        const int k0b = kc * 128;                       // byte offset into the K row
        // A hi|lo : 2 x 128 rows x 8 chunks of 16B = 2048 ops
        #pragma unroll
        for (int v = 0; v < 8; v++) {
            const int idx  = v * 256 + tid;
            const int half = idx >> 10, r = (idx >> 3) & 127, j = idx & 7;
            const int off  = k0b + j * 16;
            const char* src = (const char*)(half ? s.Alo : s.Ahi);
            const int nb = (off + 16 <= Kb) ? 16 : 0;
            const char* p = nb ? src + (size_t)(m0 + r) * Kb + off : src;
            cpa16(base + half * ASZ + r * RSB + j * 16, p, nb);
        }
        // W hi|lo : 2 x 64 rows x 8 chunks = 1024 ops
        #pragma unroll
        for (int v = 0; v < 4; v++) {
            const int idx  = v * 256 + tid;
            const int half = idx >> 9, r = (idx >> 3) & 63, j = idx & 7;
            const int off  = k0b + j * 16;
            const char* src = (const char*)(half ? s.Wlo : s.Whi);
            const int nb = (off + 16 <= Kb && (n0 + r) < N) ? 16 : 0;
            const char* p = nb ? src + (size_t)(n0 + r) * Kb + off : src;
            cpa16(base + 2 * ASZ + half * WSZ + r * RSB + j * 16, p, nb);
        }
        CP_COMMIT();
    };

    load_stage(0);
    for (int kc = 0; kc < KC; kc++) {
        if (kc + 1 < KC) { load_stage(kc + 1); asm volatile("cp.async.wait_group 1;" ::: "memory"); }
        else             {                      asm volatile("cp.async.wait_group 0;" ::: "memory"); }
        __syncthreads();
        const uint32_t base = sb + (uint32_t)(kc & 1) * STG;

        #pragma unroll
        for (int k16 = 0; k16 < 4; k16++) {
            uint32_t a_h[2][4], a_l[2][4], b_h[2][4], b_l[2][4];
            const uint32_t Ah0 = base + (wm * 32 + arow) * RSB + k16 * 32 + akoff;
            ldsm4(a_h[0], Ah0);           ldsm4(a_h[1], Ah0 + 16 * RSB);
            ldsm4(a_l[0], Ah0 + ASZ);     ldsm4(a_l[1], Ah0 + ASZ + 16 * RSB);
            const uint32_t Wh0 = base + 2 * ASZ + (wn * 32 + brow) * RSB + k16 * 32 + bkoff;
            ldsm4(b_h[0], Wh0);           ldsm4(b_h[1], Wh0 + 16 * RSB);
            ldsm4(b_l[0], Wh0 + WSZ);     ldsm4(b_l[1], Wh0 + WSZ + 16 * RSB);

            #pragma unroll
            for (int tm = 0; tm < 2; tm++)
                #pragma unroll
                for (int g = 0; g < 2; g++)
                    #pragma unroll
                    for (int sub = 0; sub < 2; sub++) {
                        float* d = acc[tm][g * 2 + sub];
                        mma16816(d, a_h[tm], &b_h[g][sub * 2]);   // Ah*Wh
                        mma16816(d, a_h[tm], &b_l[g][sub * 2]);   // Ah*Wl
                        mma16816(d, a_l[tm], &b_h[g][sub * 2]);   // Al*Wh
                    }
        }
        __syncthreads();
    }

    // ---------------- fused epilogue from fragments ----------------
    #pragma unroll
    for (int nt = 0; nt < 4; nt++) {
        const int gc = n0 + wn * 32 + nt * 8 + ((lane & 3) << 1);
        if (gc >= N) continue;
        const float b0 = s.bias ? s.bias[gc]     : 0.f;
        const float b1 = s.bias ? s.bias[gc + 1] : 0.f;
        #pragma unroll
        for (int tm = 0; tm < 2; tm++) {
            const int r0 = m0 + wm * 32 + tm * 16 + (lane >> 2);
            #pragma unroll
            for (int hh = 0; hh < 2; hh++) {
                const int gr = r0 + hh * 8;
                float v0 = acc[tm][nt][hh * 2 + 0] + b0;
                float v1 = acc[tm][nt][hh * 2 + 1] + b1;
                if (s.extra) {
                    v0 += s.extra[(size_t)gr * N + gc];
                    v1 += s.extra[(size_t)gr * N + gc + 1];
                }
                if (act) { v0 = eluf(v0); v1 = eluf(v1); }
                if (s.Cf) {
                    s.Cf[(size_t)gr * N + gc]     = v0;
                    s.Cf[(size_t)gr * N + gc + 1] = v1;
                }
                if (s.Chi) {
                    const __nv_bfloat16 h0 = __float2bfloat16(v0);
                    const __nv_bfloat16 h1 = __float2bfloat16(v1);
                    s.Chi[(size_t)gr * N + gc]     = h0;
                    s.Chi[(size_t)gr * N + gc + 1] = h1;
                    s.Clo[(size_t)gr * N + gc]     = __float2bfloat16(v0 - __bfloat162float(h0));
                    s.Clo[(size_t)gr * N + gc + 1] = __float2bfloat16(v1 - __bfloat162float(h1));
                }
            }
        }
    }
}

// ---------------- prep: fp32 -> bf16 hi/lo split ----------------
__global__ void wprep(const float* __restrict__ src, int pitch, int c0, int rows, int K,
                      __nv_bfloat16* __restrict__ hi, __nv_bfloat16* __restrict__ lo)
{
    const int total = rows * K;
    for (int i = blockIdx.x * blockDim.x + threadIdx.x; i < total; i += gridDim.x * blockDim.x) {
        const float v = src[(size_t)(i / K) * pitch + c0 + (i % K)];
        const __nv_bfloat16 h = __float2bfloat16(v);
        hi[i] = h;
        lo[i] = __float2bfloat16(v - __bfloat162float(h));
    }
}

// ---------------- rnn_in: coalesced b-tile version ----------------
// block: 256 threads, 16 batch rows; out coalesced via smem staging
__global__ void __launch_bounds__(256)
rnn_in_kernel(const float* __restrict__ act, const float* __restrict__ stoch,
              const float* __restrict__ W_in, const float* __restrict__ b_in,
              __nv_bfloat16* __restrict__ ohi, __nv_bfloat16* __restrict__ olo)
{
    __shared__ float s_in[16][38];                 // [act(6) | stoch(32)] per row
    __shared__ __nv_bfloat16 s_hi[16 * 600], s_lo[16 * 600];
    const int tid = threadIdx.x;
    const int b0 = blockIdx.x * 16;

    for (int i = tid; i < 16 * 38; i += 256) {
        const int r = i / 38, k = i % 38;
        s_in[r][k] = (k < 6) ? act[(size_t)(b0 + r) * A_DIM + k]
                             : stoch[(size_t)(b0 + r) * S_DIM + (k - 6)];
    }
    __syncthreads();

    for (int h = tid; h < H_DIM; h += 256) {
        float w[38];
        #pragma unroll
        for (int k = 0; k < 38; k++) w[k] = W_in[h * 38 + k];
        const float bias = b_in[h];
        #pragma unroll 4
        for (int b = 0; b < 16; b++) {
            float acc = bias;
            #pragma unroll
            for (int k = 0; k < 38; k++) acc = fmaf(s_in[b][k], w[k], acc);
            const float v = eluf(acc);
            const __nv_bfloat16 hh = __float2bfloat16(v);
            s_hi[b * 600 + h] = hh;
            s_lo[b * 600 + h] = __float2bfloat16(v - __bfloat162float(hh));
        }
    }
    __syncthreads();

    const size_t gbase = (size_t)b0 * H_DIM;
    for (int i = tid; i < 16 * 600; i += 256) {
        ohi[gbase + i] = s_hi[i];
        olo[gbase + i] = s_lo[i];
    }
}

// ---------------- GRU gates ----------------
__global__ void gru_gate_kernel(const float* __restrict__ gi, const float* __restrict__ gh,
                                const float* __restrict__ det_prev,
                                float* __restrict__ o1, float* __restrict__ o2,
                                __nv_bfloat16* __restrict__ dhi, __nv_bfloat16* __restrict__ dlo)
{
    const int idx = blockIdx.x * blockDim.x + threadIdx.x;
    if (idx >= BB * D_DIM) return;
    const int b = idx / D_DIM, j = idx % D_DIM;
    const float* gib = gi + (size_t)b * G3_DIM;
    const float* ghb = gh + (size_t)b * G3_DIM;
    const float r = sigmoidf_(gib[j] + ghb[j]);
    const float z = sigmoidf_(gib[D_DIM + j] + ghb[D_DIM + j]);
    const float n = tanhf(gib[2 * D_DIM + j] + r * ghb[2 * D_DIM + j]);
    const float d = (1.f - z) * n + z * det_prev[idx];
    o1[idx] = d; o2[idx] = d;
    const __nv_bfloat16 hh = __float2bfloat16(d);
    dhi[idx] = hh;
    dlo[idx] = __float2bfloat16(d - __bfloat162float(hh));
}

// ---------------- distribution heads epilogue ----------------
__global__ void dist_kernel(const float* __restrict__ oP, const float* __restrict__ oQ,
                            const float* __restrict__ ep, const float* __restrict__ eq,
                            float* __restrict__ pm_o, float* __restrict__ ps_o, float* __restrict__ pr_o,
                            float* __restrict__ qm_o, float* __restrict__ qs_o, float* __restrict__ po_o)
{
    const int idx = blockIdx.x * blockDim.x + threadIdx.x;
    if (idx >= BB * S_DIM) return;
    const int b = idx / S_DIM, sx = idx % S_DIM;
    const float pm = oP[(size_t)b * 64 + sx];
    const float ps = softplusf_(oP[(size_t)b * 64 + 32 + sx]) + MIN_STD;
    pm_o[idx] = pm; ps_o[idx] = ps; pr_o[idx] = fmaf(ps, ep[idx], pm);
    const float qm = oQ[(size_t)b * 64 + sx];
    const float qs = softplusf_(oQ[(size_t)b * 64 + 32 + sx]) + MIN_STD;
    qm_o[idx] = qm; qs_o[idx] = qs; po_o[idx] = fmaf(qs, eq[idx], qm);
}

// ---------------- host launcher ----------------
extern "C" void kernel_launch(void* const* d_in, const int* in_sizes, int n_in,
                              void* d_out, int out_size) {
    const float* encoded    = (const float*)d_in[1];
    const float* actions    = (const float*)d_in[2];
    const float* init_stoch = (const float*)d_in[3];
    const float* init_det   = (const float*)d_in[4];
    const float* noise_p    = (const float*)d_in[5];
    const float* noise_q    = (const float*)d_in[6];
    const float* W_in = (const float*)d_in[7];
    const float* b_in = (const float*)d_in[8];
    const float* W_ih = (const float*)d_in[9];
    const float* W_hh = (const float*)d_in[10];
    const float* b_ih = (const float*)d_in[11];
    const float* b_hh = (const float*)d_in[12];
    const float* Wp1  = (const float*)d_in[13];
    const float* bp1  = (const float*)d_in[14];
    const float* Wp2  = (const float*)d_in[15];
    const float* bp2  = (const float*)d_in[16];
    const float* Wq1  = (const float*)d_in[17];
    const float* bq1  = (const float*)d_in[18];
    const float* Wq2  = (const float*)d_in[19];
    const float* bq2  = (const float*)d_in[20];
    float* out = (float*)d_out;

    __nv_bfloat16 *Wih_h, *Wih_l, *Whh_h, *Whh_l, *Wp1_h, *Wp1_l, *Wq1d_h, *Wq1d_l;
    __nv_bfloat16 *Wq1e_h, *Wq1e_l, *Wp2_h, *Wp2_l, *Wq2_h, *Wq2_l;
    __nv_bfloat16 *enc_h, *enc_l, *rnn_h, *rnn_l, *det_h, *det_l, *hp_h, *hp_l, *hq_h, *hq_l;
    float *genc, *gi, *gh, *oP, *oQ;
    cudaGetSymbolAddress((void**)&Wih_h, g_Wih_h);   cudaGetSymbolAddress((void**)&Wih_l, g_Wih_l);
    cudaGetSymbolAddress((void**)&Whh_h, g_Whh_h);   cudaGetSymbolAddress((void**)&Whh_l, g_Whh_l);
    cudaGetSymbolAddress((void**)&Wp1_h, g_Wp1_h);   cudaGetSymbolAddress((void**)&Wp1_l, g_Wp1_l);
    cudaGetSymbolAddress((void**)&Wq1d_h, g_Wq1d_h); cudaGetSymbolAddress((void**)&Wq1d_l, g_Wq1d_l);
    cudaGetSymbolAddress((void**)&Wq1e_h, g_Wq1e_h); cudaGetSymbolAddress((void**)&Wq1e_l, g_Wq1e_l);
    cudaGetSymbolAddress((void**)&Wp2_h, g_Wp2_h);   cudaGetSymbolAddress((void**)&Wp2_l, g_Wp2_l);
    cudaGetSymbolAddress((void**)&Wq2_h, g_Wq2_h);   cudaGetSymbolAddress((void**)&Wq2_l, g_Wq2_l);
    cudaGetSymbolAddress((void**)&enc_h, g_enc_h);   cudaGetSymbolAddress((void**)&enc_l, g_enc_l);
    cudaGetSymbolAddress((void**)&rnn_h, g_rnn_h);   cudaGetSymbolAddress((void**)&rnn_l, g_rnn_l);
    cudaGetSymbolAddress((void**)&det_h, g_det_h);   cudaGetSymbolAddress((void**)&det_l, g_det_l);
    cudaGetSymbolAddress((void**)&hp_h, g_hp_h);     cudaGetSymbolAddress((void**)&hp_l, g_hp_l);
    cudaGetSymbolAddress((void**)&hq_h, g_hq_h);     cudaGetSymbolAddress((void**)&hq_l, g_hq_l);
    cudaGetSymbolAddress((void**)&genc, g_genc);
    cudaGetSymbolAddress((void**)&gi, g_gi);         cudaGetSymbolAddress((void**)&gh, g_gh);
    cudaGetSymbolAddress((void**)&oP, g_oP);         cudaGetSymbolAddress((void**)&oQ, g_oQ);

    cudaFuncSetAttribute(mma_gemm, cudaFuncAttributeMaxDynamicSharedMemorySize, SMEM_GEMM);

    // ---- once-per-replay prep: bf16 hi/lo splits ----
    wprep<<<4096, 256>>>(W_ih, D_DIM, 0, G3_DIM, D_DIM, Wih_h, Wih_l);
    wprep<<<4096, 256>>>(W_hh, D_DIM, 0, G3_DIM, D_DIM, Whh_h, Whh_l);
    wprep<<<2048, 256>>>(Wp1, D_DIM, 0, H_DIM, D_DIM, Wp1_h, Wp1_l);
    wprep<<<2048, 256>>>(Wq1, D_DIM + E_DIM, 0, H_DIM, D_DIM, Wq1d_h, Wq1d_l);
    wprep<<<2048, 256>>>(Wq1, D_DIM + E_DIM, D_DIM, H_DIM, E_DIM, Wq1e_h, Wq1e_l);
    wprep<<<256, 256>>>(Wp2, H_DIM, 0, 64, H_DIM, Wp2_h, Wp2_l);
    wprep<<<256, 256>>>(Wq2, H_DIM, 0, 64, H_DIM, Wq2_h, Wq2_l);
    wprep<<<16384, 256>>>(encoded, E_DIM, 0, T_STEPS * BB, E_DIM, enc_h, enc_l);
    wprep<<<2048, 256>>>(init_det, D_DIM, 0, BB, D_DIM, det_h, det_l);

    // ---- precompute genc = encoded @ Wq1[:,600:]^T   [51200 x 600], K=1024 ----
    {
        TSet s{enc_h, enc_l, Wq1e_h, Wq1e_l, nullptr, nullptr, genc, nullptr, nullptr};
        mma_gemm<<<dim3(10, T_STEPS * BB / BMT, 1), 256, SMEM_GEMM>>>(s, s, H_DIM, E_DIM, 16, 0);
    }

    // ---- sequential rollout ----
    for (int t = 0; t < T_STEPS; t++) {
        const float* stoch_prev = (t == 0) ? init_stoch : out + OFF_POST + (size_t)(t - 1) * BB * S_DIM;
        const float* det_prev_f = (t == 0) ? init_det   : out + OFF_DET1 + (size_t)(t - 1) * BB * D_DIM;
        float* det1 = out + OFF_DET1 + (size_t)t * BB * D_DIM;
        float* det2 = out + OFF_DET2 + (size_t)t * BB * D_DIM;

        rnn_in_kernel<<<BB / 16, 256>>>(
            actions + (size_t)t * BB * A_DIM, stoch_prev, W_in, b_in, rnn_h, rnn_l);

        {   // gi = rnn @ W_ih^T + b_ih ; gh = det_prev @ W_hh^T + b_hh   (N=1800, K=600)
            TSet sA{rnn_h, rnn_l, Wih_h, Wih_l, b_ih, nullptr, gi, nullptr, nullptr};
            TSet sB{det_h, det_l, Whh_h, Whh_l, b_hh, nullptr, gh, nullptr, nullptr};
            mma_gemm<<<dim3(29, BB / BMT, 2), 256, SMEM_GEMM>>>(sA, sB, G3_DIM, D_DIM, 10, 0);
        }

        gru_gate_kernel<<<(BB * D_DIM + 255) / 256, 256>>>(gi, gh, det_prev_f, det1, det2, det_h, det_l);

        {   // hp = elu(det @ Wp1^T + bp1) ; hq = elu(det @ Wq1d^T + genc_t + bq1)   (N=600, K=600)
            TSet sP{det_h, det_l, Wp1_h, Wp1_l, bp1, nullptr, nullptr, hp_h, hp_l};
            TSet sQ{det_h, det_l, Wq1d_h, Wq1d_l, bq1, genc + (size_t)t * BB * D_DIM, nullptr, hq_h, hq_l};
            mma_gemm<<<dim3(10, BB / BMT, 2), 256, SMEM_GEMM>>>(sP, sQ, H_DIM, D_DIM, 10, 1);
        }

        {   // oP = hp @ Wp2^T + bp2 ; oQ = hq @ Wq2^T + bq2   (N=64, K=600)
            TSet sP{hp_h, hp_l, Wp2_h, Wp2_l, bp2, nullptr, oP, nullptr, nullptr};
            TSet sQ{hq_h, hq_l, Wq2_h, Wq2_l, bq2, nullptr, oQ, nullptr, nullptr};
            mma_gemm<<<dim3(1, BB / BMT, 2), 256, SMEM_GEMM>>>(sP, sQ, 64, H_DIM, 10, 0);
        }

        dist_kernel<<<(BB * S_DIM + 255) / 256, 256>>>(
            oP, oQ,
            noise_p + (size_t)t * BB * S_DIM, noise_q + (size_t)t * BB * S_DIM,
            out + OFF_PM    + (size_t)t * BB * S_DIM,
            out + OFF_PS    + (size_t)t * BB * S_DIM,
            out + OFF_PRIOR + (size_t)t * BB * S_DIM,
            out + OFF_QM    + (size_t)t * BB * S_DIM,
            out + OFF_QS    + (size_t)t * BB * S_DIM,
            out + OFF_POST  + (size_t)t * BB * S_DIM);
    }
}